// round 13
// baseline (speedup 1.0000x reference)
#include <cuda_runtime.h>
#include <cuda_bf16.h>
#include <math.h>

#define HIDDEN 768
#define HEADS  12
#define DK     64
#define BATCH  8
#define SEQ    512
#define ORDERS 3
#define NEGV   -1e9f
#define K2     (768 * 768)
#define NQKV   (BATCH * HEADS * SEQ * DK)

// q/k/v stored as SPLIT PLANES: hi (bf16 of x) and lo (bf16 of x - hi)
__device__ __nv_bfloat16 g_qhH[NQKV], g_qhL[NQKV];
__device__ __nv_bfloat16 g_khH[NQKV], g_khL[NQKV];
__device__ __nv_bfloat16 g_vhH[NQKV], g_vhL[NQKV];
__device__ float g_pooled[BATCH * HIDDEN];
__device__ float g_alphas[BATCH * ORDERS];
__device__ int   g_mflags;
__device__ unsigned g_packed[ORDERS * BATCH * SEQ * 16];
__device__ unsigned g_abf[BATCH * SEQ * HIDDEN];   // attn out, packed (lo<<16|hi)
__device__ unsigned g_wbf[4 * K2];                 // weights, packed (lo<<16|hi)

__device__ __forceinline__ unsigned packbf(float x) {
    __nv_bfloat16 h = __float2bfloat16_rn(x);
    float hf = __bfloat162float(h);
    __nv_bfloat16 l = __float2bfloat16_rn(x - hf);
    return ((unsigned)__bfloat16_as_ushort(l) << 16) | (unsigned)__bfloat16_as_ushort(h);
}

#define LDSM4(R, addr) \
    asm volatile("ldmatrix.sync.aligned.m8n8.x4.shared.b16 {%0,%1,%2,%3}, [%4];" \
        : "=r"((R)[0]), "=r"((R)[1]), "=r"((R)[2]), "=r"((R)[3]) : "r"(addr))
#define LDSM4T(R, addr) \
    asm volatile("ldmatrix.sync.aligned.m8n8.x4.trans.shared.b16 {%0,%1,%2,%3}, [%4];" \
        : "=r"((R)[0]), "=r"((R)[1]), "=r"((R)[2]), "=r"((R)[3]) : "r"(addr))
#define MMABF(C, A, B0, B1) \
    asm volatile("mma.sync.aligned.m16n8k16.row.col.f32.bf16.bf16.f32 " \
        "{%0,%1,%2,%3},{%4,%5,%6,%7},{%8,%9},{%0,%1,%2,%3};" \
        : "+f"((C)[0]), "+f"((C)[1]), "+f"((C)[2]), "+f"((C)[3]) \
        : "r"((A)[0]), "r"((A)[1]), "r"((A)[2]), "r"((A)[3]), "r"(B0), "r"(B1))
#define CPA16(s, g) \
    asm volatile("cp.async.cg.shared.global [%0], [%1], 16;" :: "r"(s), "l"(g) : "memory")
#define CPA_COMMIT() asm volatile("cp.async.commit_group;" ::: "memory")
#define CPA_WAIT1()  asm volatile("cp.async.wait_group 1;" ::: "memory")
#define CPA_WAIT0()  asm volatile("cp.async.wait_group 0;" ::: "memory")

// ---- weight conversion ----
__global__ __launch_bounds__(256) void conv_w(const float* __restrict__ wq,
                                              const float* __restrict__ wk,
                                              const float* __restrict__ wv,
                                              const float* __restrict__ wm) {
    int z = blockIdx.y;
    const float* src = (z == 0) ? wq : (z == 1) ? wk : (z == 2) ? wv : wm;
    unsigned* dst = g_wbf + (size_t)z * K2;
    size_t i = (size_t)blockIdx.x * 256 + threadIdx.x;
    float4 x = ((const float4*)src)[i];
    ((uint4*)dst)[i] = make_uint4(packbf(x.x), packbf(x.y), packbf(x.z), packbf(x.w));
}

// ---- mask detection (parallel) + packing ----
__global__ void zero_flags() { g_mflags = 0; }
__global__ __launch_bounds__(256) void detect_mask_mode(const unsigned* __restrict__ m) {
    __shared__ int sflags;
    if (threadIdx.x == 0) sflags = 0;
    __syncthreads();
    int local = 0;
    int base = blockIdx.x * 1024;
    #pragma unroll
    for (int i = 0; i < 4; i++) {
        unsigned w = m[base + threadIdx.x + i * 256];
        if (w == 0x3F800000u) local |= 1;
        else if (w != 0u && w != 1u) local |= 2;
    }
    if (local) atomicOr(&sflags, local);
    __syncthreads();
    if (threadIdx.x == 0 && sflags) atomicOr(&g_mflags, sflags);
}
__global__ __launch_bounds__(256) void pack_masks(const void* __restrict__ masks) {
    int flags = g_mflags;
    int mode = (flags & 1) ? 2 : ((flags & 2) ? 0 : 1);
    int warp = threadIdx.x >> 5, lane = threadIdx.x & 31;
    int row = blockIdx.x * 8 + warp;
    size_t base = (size_t)row * SEQ;
    #pragma unroll 4
    for (int w16 = 0; w16 < 16; w16++) {
        int c = w16 * 32 + lane;
        bool bit;
        if (mode == 1)      bit = ((const int*)masks)[base + c] != 0;
        else if (mode == 2) bit = ((const float*)masks)[base + c] != 0.f;
        else                bit = ((const unsigned char*)masks)[base + c] != 0;
        unsigned bal = __ballot_sync(0xffffffffu, bit);
        if (lane == 0) g_packed[row * 16 + w16] = bal;
    }
}

// ---- routing 1 ----
__global__ __launch_bounds__(256) void route_pool(const float* __restrict__ v,
                                                  const float* __restrict__ pool_w,
                                                  const float* __restrict__ pool_b) {
    int b = blockIdx.x;
    int tid = threadIdx.x, warp = tid >> 5, lane = tid & 31;
    __shared__ float sc[SEQ];
    __shared__ float red[8], red2[8];
    __shared__ float pw[HIDDEN];
    for (int d = tid; d < HIDDEN; d += 256) pw[d] = pool_w[d];
    __syncthreads();
    for (int n = warp; n < SEQ; n += 8) {
        const float* vp = v + ((size_t)b * SEQ + n) * HIDDEN;
        float dot = 0.f, asum = 0.f;
        #pragma unroll 4
        for (int d = lane; d < HIDDEN; d += 32) {
            float x = vp[d];
            dot += x * pw[d];
            asum += fabsf(x);
        }
        #pragma unroll
        for (int o = 16; o; o >>= 1) {
            dot  += __shfl_xor_sync(0xffffffffu, dot, o);
            asum += __shfl_xor_sync(0xffffffffu, asum, o);
        }
        if (lane == 0) sc[n] = (asum == 0.f) ? NEGV : (dot + pool_b[0]);
    }
    __syncthreads();
    float m = fmaxf(sc[tid], sc[tid + 256]);
    #pragma unroll
    for (int o = 16; o; o >>= 1) m = fmaxf(m, __shfl_xor_sync(0xffffffffu, m, o));
    if (lane == 0) red[warp] = m;
    __syncthreads();
    if (tid == 0) {
        float t = red[0];
        for (int i = 1; i < 8; i++) t = fmaxf(t, red[i]);
        red[0] = t;
    }
    __syncthreads();
    m = red[0];
    float e0 = __expf(sc[tid] - m), e1 = __expf(sc[tid + 256] - m);
    float s = e0 + e1;
    #pragma unroll
    for (int o = 16; o; o >>= 1) s += __shfl_xor_sync(0xffffffffu, s, o);
    if (lane == 0) red2[warp] = s;
    __syncthreads();
    if (tid == 0) {
        float t = 0.f;
        for (int i = 0; i < 8; i++) t += red2[i];
        red2[0] = t;
    }
    __syncthreads();
    float inv = 1.f / red2[0];
    sc[tid] = e0 * inv;
    sc[tid + 256] = e1 * inv;
    __syncthreads();
    float a0 = 0.f, a1 = 0.f, a2 = 0.f;
    #pragma unroll 4
    for (int n = 0; n < SEQ; n++) {
        float p = sc[n];
        const float* vp = v + ((size_t)b * SEQ + n) * HIDDEN;
        a0 += vp[tid] * p;
        a1 += vp[tid + 256] * p;
        a2 += vp[tid + 512] * p;
    }
    g_pooled[b * HIDDEN + tid]       = a0;
    g_pooled[b * HIDDEN + tid + 256] = a1;
    g_pooled[b * HIDDEN + tid + 512] = a2;
}

// ---- routing 2 ----
__global__ __launch_bounds__(384) void route_mlp(const float* __restrict__ w1,
                                                 const float* __restrict__ w2,
                                                 const float* __restrict__ b2) {
    int b = blockIdx.x, tid = threadIdx.x;
    __shared__ float pl[HIDDEN];
    __shared__ float pred[12 * 3];
    for (int d = tid; d < HIDDEN; d += 384) pl[d] = g_pooled[b * HIDDEN + d];
    __syncthreads();
    float acc = 0.f;
    #pragma unroll 16
    for (int k = 0; k < HIDDEN; k++) acc += pl[k] * __ldg(&w1[k * 384 + tid]);
    float hv = fmaxf(acc, 0.f);
    float p0 = hv * w2[tid * 3 + 0];
    float p1 = hv * w2[tid * 3 + 1];
    float p2 = hv * w2[tid * 3 + 2];
    #pragma unroll
    for (int o = 16; o; o >>= 1) {
        p0 += __shfl_xor_sync(0xffffffffu, p0, o);
        p1 += __shfl_xor_sync(0xffffffffu, p1, o);
        p2 += __shfl_xor_sync(0xffffffffu, p2, o);
    }
    int warp = tid >> 5;
    if ((tid & 31) == 0) { pred[warp*3] = p0; pred[warp*3+1] = p1; pred[warp*3+2] = p2; }
    __syncthreads();
    if (tid == 0) {
        float l0 = b2[0], l1 = b2[1], l2 = b2[2];
        for (int w = 0; w < 12; w++) { l0 += pred[w*3]; l1 += pred[w*3+1]; l2 += pred[w*3+2]; }
        float mm = fmaxf(l0, fmaxf(l1, l2));
        float e0 = __expf(l0 - mm), e1 = __expf(l1 - mm), e2 = __expf(l2 - mm);
        float z = e0 + e1 + e2;
        g_alphas[b*3+0] = e0 / z; g_alphas[b*3+1] = e1 / z; g_alphas[b*3+2] = e2 / z;
    }
}

// ---- bf16-split tensor-core GEMM, software-pipelined global loads ----
// xfmt 0: X packed (lo<<16|hi); xfmt 1: X fp32 (converted inline)
// omode 0: fp32 out[i*768+j] (outA); omode 1: split planes outA=hi outB=lo, head layout
__device__ __forceinline__ void gemm_bf_body(const void* __restrict__ Xv, int xfmt,
                                             const unsigned* __restrict__ Wp,
                                             const float* __restrict__ bias,
                                             void* __restrict__ outA,
                                             void* __restrict__ outB,
                                             float scale, int omode,
                                             int row0, int col0) {
    __shared__ __align__(16) __nv_bfloat16 Ah[128][40], Al[128][40];
    __shared__ __align__(16) __nv_bfloat16 Bh[32][136], Bl[32][136];
    int tid = threadIdx.x;
    int wid = tid >> 5, lane = tid & 31;
    int wm = wid & 1, wn = wid >> 1;

    float acc[4][4][4];
    #pragma unroll
    for (int i = 0; i < 4; i++)
        #pragma unroll
        for (int j = 0; j < 4; j++)
            #pragma unroll
            for (int c = 0; c < 4; c++) acc[i][j][c] = 0.f;

    unsigned aaddr_h[4], aaddr_l[4];
    #pragma unroll
    for (int mt = 0; mt < 4; mt++) {
        aaddr_h[mt] = (unsigned)__cvta_generic_to_shared(
            &Ah[wm * 64 + mt * 16 + (lane & 15)][(lane >> 4) << 3]);
        aaddr_l[mt] = (unsigned)__cvta_generic_to_shared(
            &Al[wm * 64 + mt * 16 + (lane & 15)][(lane >> 4) << 3]);
    }
    unsigned baddr_h[2], baddr_l[2];
    #pragma unroll
    for (int nb = 0; nb < 2; nb++) {
        int kr = (lane & 7) + (((lane >> 3) & 1) << 3);
        int nc = wn * 32 + nb * 16 + ((lane >> 4) << 3);
        baddr_h[nb] = (unsigned)__cvta_generic_to_shared(&Bh[kr][nc]);
        baddr_l[nb] = (unsigned)__cvta_generic_to_shared(&Bl[kr][nc]);
    }

    // per-thread fill coordinates
    int ar[4], ak[4], bk[4], bn[4];
    #pragma unroll
    for (int i = 0; i < 4; i++) {
        int e = tid + i * 256;
        ar[i] = e >> 3;  ak[i] = (e & 7) * 4;
        bk[i] = e >> 5;  bn[i] = (e & 31) * 4;
    }

    // register prefetch buffers
    float4 raf[4];   // xfmt=1
    uint4  rau[4];   // xfmt=0
    uint4  rbu[4];

    // prefetch kt = 0
    if (xfmt == 1) {
        const float* Xf = (const float*)Xv;
        #pragma unroll
        for (int i = 0; i < 4; i++)
            raf[i] = *(const float4*)&Xf[(size_t)(row0 + ar[i]) * 768 + ak[i]];
    } else {
        const unsigned* Xp = (const unsigned*)Xv;
        #pragma unroll
        for (int i = 0; i < 4; i++)
            rau[i] = *(const uint4*)&Xp[(size_t)(row0 + ar[i]) * 768 + ak[i]];
    }
    #pragma unroll
    for (int i = 0; i < 4; i++)
        rbu[i] = *(const uint4*)&Wp[(size_t)bk[i] * 768 + col0 + bn[i]];

    for (int kt = 0; kt < 768; kt += 32) {
        __syncthreads();   // previous MMA done reading smem
        // store phase: regs -> smem (with conversion)
        if (xfmt == 1) {
            #pragma unroll
            for (int i = 0; i < 4; i++) {
                unsigned p0 = packbf(raf[i].x), p1 = packbf(raf[i].y);
                unsigned p2 = packbf(raf[i].z), p3 = packbf(raf[i].w);
                *(unsigned*)&Ah[ar[i]][ak[i]]     = __byte_perm(p0, p1, 0x5410);
                *(unsigned*)&Al[ar[i]][ak[i]]     = __byte_perm(p0, p1, 0x7632);
                *(unsigned*)&Ah[ar[i]][ak[i] + 2] = __byte_perm(p2, p3, 0x5410);
                *(unsigned*)&Al[ar[i]][ak[i] + 2] = __byte_perm(p2, p3, 0x7632);
            }
        } else {
            #pragma unroll
            for (int i = 0; i < 4; i++) {
                *(unsigned*)&Ah[ar[i]][ak[i]]     = __byte_perm(rau[i].x, rau[i].y, 0x5410);
                *(unsigned*)&Al[ar[i]][ak[i]]     = __byte_perm(rau[i].x, rau[i].y, 0x7632);
                *(unsigned*)&Ah[ar[i]][ak[i] + 2] = __byte_perm(rau[i].z, rau[i].w, 0x5410);
                *(unsigned*)&Al[ar[i]][ak[i] + 2] = __byte_perm(rau[i].z, rau[i].w, 0x7632);
            }
        }
        #pragma unroll
        for (int i = 0; i < 4; i++) {
            *(unsigned*)&Bh[bk[i]][bn[i]]     = __byte_perm(rbu[i].x, rbu[i].y, 0x5410);
            *(unsigned*)&Bl[bk[i]][bn[i]]     = __byte_perm(rbu[i].x, rbu[i].y, 0x7632);
            *(unsigned*)&Bh[bk[i]][bn[i] + 2] = __byte_perm(rbu[i].z, rbu[i].w, 0x5410);
            *(unsigned*)&Bl[bk[i]][bn[i] + 2] = __byte_perm(rbu[i].z, rbu[i].w, 0x7632);
        }
        __syncthreads();
        // prefetch next kt (LDG latency hidden behind MMA below)
        if (kt < 736) {
            int kn = kt + 32;
            if (xfmt == 1) {
                const float* Xf = (const float*)Xv;
                #pragma unroll
                for (int i = 0; i < 4; i++)
                    raf[i] = *(const float4*)&Xf[(size_t)(row0 + ar[i]) * 768 + kn + ak[i]];
            } else {
                const unsigned* Xp = (const unsigned*)Xv;
                #pragma unroll
                for (int i = 0; i < 4; i++)
                    rau[i] = *(const uint4*)&Xp[(size_t)(row0 + ar[i]) * 768 + kn + ak[i]];
            }
            #pragma unroll
            for (int i = 0; i < 4; i++)
                rbu[i] = *(const uint4*)&Wp[(size_t)(kn + bk[i]) * 768 + col0 + bn[i]];
        }
        // MMA phase
        #pragma unroll
        for (int ks = 0; ks < 2; ks++) {
            unsigned koff = ks * 32;
            unsigned ah[4][4], al[4][4], bh[2][4], bl[2][4];
            #pragma unroll
            for (int mt = 0; mt < 4; mt++) {
                LDSM4(ah[mt], aaddr_h[mt] + koff);
                LDSM4(al[mt], aaddr_l[mt] + koff);
            }
            #pragma unroll
            for (int nb = 0; nb < 2; nb++) {
                LDSM4T(bh[nb], baddr_h[nb] + ks * 16 * 272);
                LDSM4T(bl[nb], baddr_l[nb] + ks * 16 * 272);
            }
            #pragma unroll
            for (int mt = 0; mt < 4; mt++)
                #pragma unroll
                for (int nt = 0; nt < 4; nt++) {
                    unsigned bh0 = bh[nt >> 1][(nt & 1) * 2];
                    unsigned bh1 = bh[nt >> 1][(nt & 1) * 2 + 1];
                    unsigned bl0 = bl[nt >> 1][(nt & 1) * 2];
                    unsigned bl1 = bl[nt >> 1][(nt & 1) * 2 + 1];
                    MMABF(acc[mt][nt], ah[mt], bh0, bh1);
                    MMABF(acc[mt][nt], ah[mt], bl0, bl1);
                    MMABF(acc[mt][nt], al[mt], bh0, bh1);
                }
        }
    }

    int rbase = row0 + wm * 64, cbase = col0 + wn * 32;
    #pragma unroll
    for (int mt = 0; mt < 4; mt++) {
        #pragma unroll
        for (int nt = 0; nt < 4; nt++) {
            int gj = cbase + nt * 8 + (lane & 3) * 2;
            float b0 = __ldg(&bias[gj]), b1 = __ldg(&bias[gj + 1]);
            int r_lo = rbase + mt * 16 + (lane >> 2);
            int r_hi = r_lo + 8;
            float c00 = (acc[mt][nt][0] + b0) * scale;
            float c01 = (acc[mt][nt][1] + b1) * scale;
            float c10 = (acc[mt][nt][2] + b0) * scale;
            float c11 = (acc[mt][nt][3] + b1) * scale;
            if (omode == 1) {
                __nv_bfloat16* ohi = (__nv_bfloat16*)outA;
                __nv_bfloat16* olo = (__nv_bfloat16*)outB;
                unsigned p00 = packbf(c00), p01 = packbf(c01);
                unsigned p10 = packbf(c10), p11 = packbf(c11);
                int bb0 = r_lo >> 9, n0 = r_lo & 511;
                int h = gj >> 6, d = gj & 63;
                size_t o0 = (((size_t)bb0 * HEADS + h) * SEQ + n0) * DK + d;
                *(ushort2*)&ohi[o0] = make_ushort2((unsigned short)p00, (unsigned short)p01);
                *(ushort2*)&olo[o0] = make_ushort2((unsigned short)(p00 >> 16),
                                                   (unsigned short)(p01 >> 16));
                int bb1 = r_hi >> 9, n1 = r_hi & 511;
                size_t o1 = (((size_t)bb1 * HEADS + h) * SEQ + n1) * DK + d;
                *(ushort2*)&ohi[o1] = make_ushort2((unsigned short)p10, (unsigned short)p11);
                *(ushort2*)&olo[o1] = make_ushort2((unsigned short)(p10 >> 16),
                                                   (unsigned short)(p11 >> 16));
            } else {
                float* out = (float*)outA;
                *(float2*)&out[(size_t)r_lo * 768 + gj] = make_float2(c00, c01);
                *(float2*)&out[(size_t)r_hi * 768 + gj] = make_float2(c10, c11);
            }
        }
    }
}

__global__ __launch_bounds__(256) void gemm_qkv_bf(const float* __restrict__ q,
                                                   const float* __restrict__ k,
                                                   const float* __restrict__ v,
                                                   const float* __restrict__ bq,
                                                   const float* __restrict__ bk,
                                                   const float* __restrict__ bv) {
    int z = blockIdx.z;
    const float* X; const unsigned* Wp; const float* bias;
    __nv_bfloat16 *oh, *ol; float scale;
    if (z == 0)      { X = q; Wp = g_wbf;          bias = bq; oh = g_qhH; ol = g_qhL; scale = 0.125f; }
    else if (z == 1) { X = k; Wp = g_wbf + K2;     bias = bk; oh = g_khH; ol = g_khL; scale = 1.f; }
    else             { X = v; Wp = g_wbf + 2 * K2; bias = bv; oh = g_vhH; ol = g_vhL; scale = 1.f; }
    gemm_bf_body(X, 1, Wp, bias, oh, ol, scale, 1, blockIdx.y * 128, blockIdx.x * 128);
}

__global__ __launch_bounds__(256) void gemm_out_bf(const float* __restrict__ bias,
                                                   float* __restrict__ out) {
    gemm_bf_body(g_abf, 0, g_wbf + 3 * K2, bias, out, 0, 1.f, 0,
                 blockIdx.y * 128, blockIdx.x * 128);
}

// ---- fused attention: RT=32, 2 CTAs/SM, cp.async double-buffered fills ----
#define RT 32
#define SPITCH 516
#define OFF_Q  66048
#define OFF_B0 75264
#define OFF_B1 93696
#define ATTN_SMEM 112128
#define PLB 9216      // plane size within a buffer (64 x 72 x 2B)

__device__ __forceinline__ void cpa_chunk64(unsigned dst,
                                            const __nv_bfloat16* __restrict__ hi,
                                            const __nv_bfloat16* __restrict__ lo,
                                            int tid) {
    #pragma unroll
    for (int i = 0; i < 2; i++) {
        int idx = tid + i * 256;
        int r = idx >> 3, sg = idx & 7;
        CPA16(dst + r * 144 + sg * 16, hi + r * 64 + sg * 8);
    }
    #pragma unroll
    for (int i = 0; i < 2; i++) {
        int idx = tid + i * 256;
        int r = idx >> 3, sg = idx & 7;
        CPA16(dst + PLB + r * 144 + sg * 16, lo + r * 64 + sg * 8);
    }
}

__global__ __launch_bounds__(256, 2) void attn_kernel() {
    extern __shared__ char smc[];
    float* S = (float*)smc;                                  // 32 x 516 fp32
    __nv_bfloat16* AhS = (__nv_bfloat16*)(smc + OFF_Q);      // 32 x 72 (A hi, phase 3)
    __nv_bfloat16* AlS = (__nv_bfloat16*)(smc + OFF_Q + 4608);
    unsigned sb = (unsigned)__cvta_generic_to_shared(smc);

    int rt = blockIdx.x, h = blockIdx.y, b = blockIdx.z;
    int tid = threadIdx.x;
    int wid = tid >> 5, lane = tid & 31;
    int wm = wid & 1, wn = wid >> 1;    // 2 x 4 warp grid

    size_t hoff = ((size_t)(b * HEADS + h)) * SEQ * DK;
    const __nv_bfloat16* QgH = g_qhH + hoff + rt * RT * DK;
    const __nv_bfloat16* QgL = g_qhL + hoff + rt * RT * DK;
    const __nv_bfloat16* KgH = g_khH + hoff;
    const __nv_bfloat16* KgL = g_khL + hoff;
    const __nv_bfloat16* VgH = g_vhH + hoff;
    const __nv_bfloat16* VgL = g_vhL + hoff;

    unsigned bufb0 = sb + OFF_B0, bufb1 = sb + OFF_B1;

    unsigned qrow = (wm * 16 + (lane & 15)) * 144 + ((lane >> 4) << 4);
    unsigned qah = sb + OFF_Q + qrow;            // Q (phase 1) / A (phase 3)
    unsigned qal = qah + 4608;
    unsigned krow = (wn * 16 + (lane & 15)) * 144 + ((lane >> 4) << 4);
    unsigned ka0h = bufb0 + krow, ka0l = ka0h + PLB;
    unsigned ka1h = bufb1 + krow, ka1l = ka1h + PLB;
    int vkr = (lane & 7) + (((lane >> 3) & 1) << 3);
    unsigned vrow = vkr * 144 + wn * 32 + ((lane >> 4) << 4);
    unsigned va0h = bufb0 + vrow, va0l = va0h + PLB;
    unsigned va1h = bufb1 + vrow, va1l = va1h + PLB;

    // prologue: Q + K0 (group), K1 (group)
    {
        int r = tid >> 3, sg = tid & 7;
        CPA16(sb + OFF_Q + r * 144 + sg * 16, QgH + r * 64 + sg * 8);
        CPA16(sb + OFF_Q + 4608 + r * 144 + sg * 16, QgL + r * 64 + sg * 8);
    }
    cpa_chunk64(bufb0, KgH, KgL, tid);
    CPA_COMMIT();
    cpa_chunk64(bufb1, KgH + 4096, KgL + 4096, tid);
    CPA_COMMIT();

    // ---- phase 1: S[32][512] = Q K^T, pipelined over 8 chunks of 64 cols ----
    unsigned qfh[4][4], qfl[4][4];
    #pragma unroll
    for (int ch = 0; ch < 8; ch++) {
        if (ch < 7) { CPA_WAIT1(); } else { CPA_WAIT0(); }
        __syncthreads();
        if (ch == 0) {
            #pragma unroll
            for (int kc = 0; kc < 4; kc++) {
                LDSM4(qfh[kc], qah + kc * 32);
                LDSM4(qfl[kc], qal + kc * 32);
            }
        }
        unsigned kh_ = (ch & 1) ? ka1h : ka0h;
        unsigned kl_ = (ch & 1) ? ka1l : ka0l;
        float acc1[2][4];
        #pragma unroll
        for (int j = 0; j < 2; j++)
            #pragma unroll
            for (int c = 0; c < 4; c++) acc1[j][c] = 0.f;
        #pragma unroll
        for (int kc = 0; kc < 4; kc++) {
            unsigned bh[4], bl[4];
            LDSM4(bh, kh_ + kc * 32);
            LDSM4(bl, kl_ + kc * 32);
            #pragma unroll
            for (int nt = 0; nt < 2; nt++) {
                MMABF(acc1[nt], qfh[kc], bh[nt], bh[nt + 2]);
                MMABF(acc1[nt], qfh[kc], bl[nt], bl[nt + 2]);
                MMABF(acc1[nt], qfl[kc], bh[nt], bh[nt + 2]);
            }
        }
        #pragma unroll
        for (int nt = 0; nt < 2; nt++) {
            int r = wm * 16 + (lane >> 2);
            int c = ch * 64 + wn * 16 + nt * 8 + (lane & 3) * 2;
            *(float2*)&S[r * SPITCH + c] = make_float2(acc1[nt][0], acc1[nt][1]);
            *(float2*)&S[(r + 8) * SPITCH + c] = make_float2(acc1[nt][2], acc1[nt][3]);
        }
        __syncthreads();
        if (ch < 6) {
            cpa_chunk64((ch & 1) ? bufb1 : bufb0,
                        KgH + (ch + 2) * 4096, KgL + (ch + 2) * 4096, tid);
            CPA_COMMIT();
        }
    }

    // prefetch V chunks 0,1 (land during phase 2)
    cpa_chunk64(bufb0, VgH, VgL, tid);
    CPA_COMMIT();
    cpa_chunk64(bufb1, VgH + 4096, VgL + 4096, tid);
    CPA_COMMIT();

    // ---- phase 2: masked softmax algebra ----
    float wa0g = __ldg(&g_alphas[b*3+0]);
    float wa1g = __ldg(&g_alphas[b*3+1]);
    float wa2g = __ldg(&g_alphas[b*3+2]);
    for (int r = wid; r < RT; r += 8) {
        float* Sr = S + r * SPITCH;
        int n = rt * RT + r;
        const unsigned* p0 = g_packed + ((size_t)(0*BATCH + b) * SEQ + n) * 16;
        const unsigned* p1 = g_packed + ((size_t)(1*BATCH + b) * SEQ + n) * 16;
        const unsigned* p2 = g_packed + ((size_t)(2*BATCH + b) * SEQ + n) * 16;

        float mx = -1e30f;
        #pragma unroll
        for (int it = 0; it < 16; it++) mx = fmaxf(mx, Sr[it * 32 + lane]);
        #pragma unroll
        for (int o = 16; o; o >>= 1) mx = fmaxf(mx, __shfl_xor_sync(0xffffffffu, mx, o));

        float z0 = 0.f, z1 = 0.f, z2 = 0.f;
        #pragma unroll
        for (int it = 0; it < 16; it++) {
            int c = it * 32 + lane;
            float e = __expf(Sr[c] - mx);
            Sr[c] = e;
            unsigned w0 = __ldg(p0 + it), w1 = __ldg(p1 + it), w2 = __ldg(p2 + it);
            if (!((w0 >> lane) & 1)) z0 += e;
            if (!((w1 >> lane) & 1)) z1 += e;
            if (!((w2 >> lane) & 1)) z2 += e;
        }
        #pragma unroll
        for (int o = 16; o; o >>= 1) {
            z0 += __shfl_xor_sync(0xffffffffu, z0, o);
            z1 += __shfl_xor_sync(0xffffffffu, z1, o);
            z2 += __shfl_xor_sync(0xffffffffu, z2, o);
        }
        float wa0 = wa0g / z0, wa1 = wa1g / z1, wa2 = wa2g / z2;
        #pragma unroll
        for (int it = 0; it < 16; it++) {
            int c = it * 32 + lane;
            unsigned w0 = __ldg(p0 + it), w1 = __ldg(p1 + it), w2 = __ldg(p2 + it);
            float coef = (((w0 >> lane) & 1) ? 0.f : wa0)
                       + (((w1 >> lane) & 1) ? 0.f : wa1)
                       + (((w2 >> lane) & 1) ? 0.f : wa2);
            Sr[c] *= coef;
        }
    }

    // ---- phase 3: O[32][64] = A V, pipelined over 8 chunks of 64 k-rows ----
    float acc3[2][4];
    #pragma unroll
    for (int j = 0; j < 2; j++)
        #pragma unroll
        for (int c = 0; c < 4; c++) acc3[j][c] = 0.f;

    #pragma unroll
    for (int ch = 0; ch < 8; ch++) {
        if (ch < 7) { CPA_WAIT1(); } else { CPA_WAIT0(); }
        __syncthreads();
        #pragma unroll
        for (int i = 0; i < 4; i++) {
            int idx = tid + i * 256;
            int r = idx >> 5, c2 = (idx & 31) * 2;
            float2 v2 = *(const float2*)&S[r * SPITCH + ch * 64 + c2];
            unsigned pa = packbf(v2.x), pb = packbf(v2.y);
            *(unsigned*)&AhS[r * 72 + c2] = __byte_perm(pa, pb, 0x5410);
            *(unsigned*)&AlS[r * 72 + c2] = __byte_perm(pa, pb, 0x7632);
        }
        __syncthreads();
        unsigned vh_ = (ch & 1) ? va1h : va0h;
        unsigned vl_ = (ch & 1) ? va1l : va0l;
        #pragma unroll
        for (int kc = 0; kc < 4; kc++) {
            unsigned koff = kc * 32, voff = kc * 2304;
            unsigned ah[4], al[4], bh[4], bl[4];
            LDSM4(ah, qah + koff);
            LDSM4(al, qal + koff);
            LDSM4T(bh, vh_ + voff);
            LDSM4T(bl, vl_ + voff);
            #pragma unroll
            for (int nt = 0; nt < 2; nt++) {
                MMABF(acc3[nt], ah, bh[nt * 2], bh[nt * 2 + 1]);
                MMABF(acc3[nt], ah, bl[nt * 2], bl[nt * 2 + 1]);
                MMABF(acc3[nt], al, bh[nt * 2], bh[nt * 2 + 1]);
            }
        }
        __syncthreads();
        if (ch < 6) {
            cpa_chunk64((ch & 1) ? bufb1 : bufb0,
                        VgH + (ch + 2) * 4096, VgL + (ch + 2) * 4096, tid);
            CPA_COMMIT();
        }
    }

    // epilogue: pack to g_abf [b*512+n][h*64+d]
    #pragma unroll
    for (int nt = 0; nt < 2; nt++) {
        int r = wm * 16 + (lane >> 2);
        int c = wn * 16 + nt * 8 + (lane & 3) * 2;
        size_t off0 = (size_t)(b * SEQ + rt * RT + r) * HIDDEN + h * 64 + c;
        size_t off1 = (size_t)(b * SEQ + rt * RT + r + 8) * HIDDEN + h * 64 + c;
        *(uint2*)&g_abf[off0] = make_uint2(packbf(acc3[nt][0]), packbf(acc3[nt][1]));
        *(uint2*)&g_abf[off1] = make_uint2(packbf(acc3[nt][2]), packbf(acc3[nt][3]));
    }
}

// ---- launch ----
extern "C" void kernel_launch(void* const* d_in, const int* in_sizes, int n_in,
                              void* d_out, int out_size) {
    const float* v = (const float*)d_in[0];
    const float* k = (const float*)d_in[1];
    const float* q = (const float*)d_in[2];
    const void*  masks = d_in[3];
    const float* Wv = (const float*)d_in[6];
    const float* bv = (const float*)d_in[7];
    const float* Wk = (const float*)d_in[8];
    const float* bk = (const float*)d_in[9];
    const float* Wq = (const float*)d_in[10];
    const float* bq = (const float*)d_in[11];
    const float* Wm = (const float*)d_in[12];
    const float* bm = (const float*)d_in[13];
    const float* pool_w = (const float*)d_in[14];
    const float* pool_b = (const float*)d_in[15];
    const float* w1 = (const float*)d_in[16];
    const float* w2 = (const float*)d_in[17];
    const float* b2 = (const float*)d_in[18];
    float* out = (float*)d_out;

    static cudaStream_t s1 = 0, s2 = 0;
    static cudaEvent_t evR = 0, ev1 = 0, ev2 = 0, ev3 = 0;
    if (!s1) {
        cudaStreamCreateWithFlags(&s1, cudaStreamNonBlocking);
        cudaStreamCreateWithFlags(&s2, cudaStreamNonBlocking);
        cudaEventCreateWithFlags(&evR, cudaEventDisableTiming);
        cudaEventCreateWithFlags(&ev1, cudaEventDisableTiming);
        cudaEventCreateWithFlags(&ev2, cudaEventDisableTiming);
        cudaEventCreateWithFlags(&ev3, cudaEventDisableTiming);
        cudaFuncSetAttribute(attn_kernel, cudaFuncAttributeMaxDynamicSharedMemorySize, ATTN_SMEM);
    }

    cudaEventRecord(evR, 0);
    cudaStreamWaitEvent(s1, evR, 0);
    cudaStreamWaitEvent(s2, evR, 0);

    // s1: routing branch
    route_pool<<<BATCH, 256, 0, s1>>>(v, pool_w, pool_b);
    route_mlp<<<BATCH, 384, 0, s1>>>(w1, w2, b2);
    cudaEventRecord(ev1, s1);

    // s2: weight conversion FIRST (gates QKV), then mask branch (parallel detect)
    conv_w<<<dim3(K2 / 1024, 4), 256, 0, s2>>>(Wq, Wk, Wv, Wm);
    cudaEventRecord(ev2, s2);
    zero_flags<<<1, 1, 0, s2>>>();
    detect_mask_mode<<<16, 256, 0, s2>>>((const unsigned*)masks);
    pack_masks<<<ORDERS * BATCH * SEQ / 8, 256, 0, s2>>>(masks);
    cudaEventRecord(ev3, s2);

    // main: QKV projections (fp32 inputs, inline split) after weights ready
    cudaStreamWaitEvent(0, ev2, 0);
    dim3 gq(HIDDEN / 128, (BATCH * SEQ) / 128, 3);
    gemm_qkv_bf<<<gq, 256>>>(q, k, v, bq, bk, bv);

    cudaStreamWaitEvent(0, ev1, 0);
    cudaStreamWaitEvent(0, ev3, 0);

    attn_kernel<<<dim3(SEQ / RT, HEADS, BATCH), 256, ATTN_SMEM>>>();

    dim3 gg(HIDDEN / 128, (BATCH * SEQ) / 128);
    gemm_out_bf<<<gg, 256>>>(bm, out);
}

// round 16
// speedup vs baseline: 1.0438x; 1.0438x over previous
#include <cuda_runtime.h>
#include <cuda_bf16.h>
#include <math.h>

#define HIDDEN 768
#define HEADS  12
#define DK     64
#define BATCH  8
#define SEQ    512
#define ORDERS 3
#define NEGV   -1e9f
#define K2     (768 * 768)
#define NQKV   (BATCH * HEADS * SEQ * DK)

// q/k/v stored as SPLIT PLANES: hi (bf16 of x) and lo (bf16 of x - hi)
__device__ __nv_bfloat16 g_qhH[NQKV], g_qhL[NQKV];
__device__ __nv_bfloat16 g_khH[NQKV], g_khL[NQKV];
__device__ __nv_bfloat16 g_vhH[NQKV], g_vhL[NQKV];
__device__ float g_pooled[BATCH * HIDDEN];
__device__ float g_alphas[BATCH * ORDERS];
__device__ int   g_mflags;
__device__ unsigned g_packed[ORDERS * BATCH * SEQ * 16];
__device__ unsigned g_abf[BATCH * SEQ * HIDDEN];           // attn out, packed (lo<<16|hi)
__device__ __nv_bfloat16 g_wH[4 * K2], g_wL[4 * K2];       // weights, split planes

__device__ __forceinline__ unsigned packbf(float x) {
    __nv_bfloat16 h = __float2bfloat16_rn(x);
    float hf = __bfloat162float(h);
    __nv_bfloat16 l = __float2bfloat16_rn(x - hf);
    return ((unsigned)__bfloat16_as_ushort(l) << 16) | (unsigned)__bfloat16_as_ushort(h);
}

#define LDSM4(R, addr) \
    asm volatile("ldmatrix.sync.aligned.m8n8.x4.shared.b16 {%0,%1,%2,%3}, [%4];" \
        : "=r"((R)[0]), "=r"((R)[1]), "=r"((R)[2]), "=r"((R)[3]) : "r"(addr))
#define LDSM4T(R, addr) \
    asm volatile("ldmatrix.sync.aligned.m8n8.x4.trans.shared.b16 {%0,%1,%2,%3}, [%4];" \
        : "=r"((R)[0]), "=r"((R)[1]), "=r"((R)[2]), "=r"((R)[3]) : "r"(addr))
#define MMABF(C, A, B0, B1) \
    asm volatile("mma.sync.aligned.m16n8k16.row.col.f32.bf16.bf16.f32 " \
        "{%0,%1,%2,%3},{%4,%5,%6,%7},{%8,%9},{%0,%1,%2,%3};" \
        : "+f"((C)[0]), "+f"((C)[1]), "+f"((C)[2]), "+f"((C)[3]) \
        : "r"((A)[0]), "r"((A)[1]), "r"((A)[2]), "r"((A)[3]), "r"(B0), "r"(B1))
#define CPA16(s, g) \
    asm volatile("cp.async.cg.shared.global [%0], [%1], 16;" :: "r"(s), "l"(g) : "memory")
#define CPA_COMMIT() asm volatile("cp.async.commit_group;" ::: "memory")
#define CPA_WAIT1()  asm volatile("cp.async.wait_group 1;" ::: "memory")
#define CPA_WAIT0()  asm volatile("cp.async.wait_group 0;" ::: "memory")

// ---- weight conversion -> split planes ----
__global__ __launch_bounds__(256) void conv_w(const float* __restrict__ wq,
                                              const float* __restrict__ wk,
                                              const float* __restrict__ wv,
                                              const float* __restrict__ wm) {
    int z = blockIdx.y;
    const float* src = (z == 0) ? wq : (z == 1) ? wk : (z == 2) ? wv : wm;
    size_t base = (size_t)z * K2;
    size_t i = ((size_t)blockIdx.x * 256 + threadIdx.x) * 4;
    float4 x = *(const float4*)&src[i];
    unsigned p0 = packbf(x.x), p1 = packbf(x.y), p2 = packbf(x.z), p3 = packbf(x.w);
    *(ushort4*)&g_wH[base + i] = make_ushort4((unsigned short)p0, (unsigned short)p1,
                                              (unsigned short)p2, (unsigned short)p3);
    *(ushort4*)&g_wL[base + i] = make_ushort4((unsigned short)(p0 >> 16), (unsigned short)(p1 >> 16),
                                              (unsigned short)(p2 >> 16), (unsigned short)(p3 >> 16));
}

// ---- mask detection (parallel) + packing ----
__global__ void zero_flags() { g_mflags = 0; }
__global__ __launch_bounds__(256) void detect_mask_mode(const unsigned* __restrict__ m) {
    __shared__ int sflags;
    if (threadIdx.x == 0) sflags = 0;
    __syncthreads();
    int local = 0;
    int base = blockIdx.x * 1024;
    #pragma unroll
    for (int i = 0; i < 4; i++) {
        unsigned w = m[base + threadIdx.x + i * 256];
        if (w == 0x3F800000u) local |= 1;
        else if (w != 0u && w != 1u) local |= 2;
    }
    if (local) atomicOr(&sflags, local);
    __syncthreads();
    if (threadIdx.x == 0 && sflags) atomicOr(&g_mflags, sflags);
}
__global__ __launch_bounds__(256) void pack_masks(const void* __restrict__ masks) {
    int flags = g_mflags;
    int mode = (flags & 1) ? 2 : ((flags & 2) ? 0 : 1);
    int warp = threadIdx.x >> 5, lane = threadIdx.x & 31;
    int row = blockIdx.x * 8 + warp;
    size_t base = (size_t)row * SEQ;
    #pragma unroll 4
    for (int w16 = 0; w16 < 16; w16++) {
        int c = w16 * 32 + lane;
        bool bit;
        if (mode == 1)      bit = ((const int*)masks)[base + c] != 0;
        else if (mode == 2) bit = ((const float*)masks)[base + c] != 0.f;
        else                bit = ((const unsigned char*)masks)[base + c] != 0;
        unsigned bal = __ballot_sync(0xffffffffu, bit);
        if (lane == 0) g_packed[row * 16 + w16] = bal;
    }
}

// ---- routing 1 ----
__global__ __launch_bounds__(256) void route_pool(const float* __restrict__ v,
                                                  const float* __restrict__ pool_w,
                                                  const float* __restrict__ pool_b) {
    int b = blockIdx.x;
    int tid = threadIdx.x, warp = tid >> 5, lane = tid & 31;
    __shared__ float sc[SEQ];
    __shared__ float red[8], red2[8];
    __shared__ float pw[HIDDEN];
    for (int d = tid; d < HIDDEN; d += 256) pw[d] = pool_w[d];
    __syncthreads();
    for (int n = warp; n < SEQ; n += 8) {
        const float* vp = v + ((size_t)b * SEQ + n) * HIDDEN;
        float dot = 0.f, asum = 0.f;
        #pragma unroll 4
        for (int d = lane; d < HIDDEN; d += 32) {
            float x = vp[d];
            dot += x * pw[d];
            asum += fabsf(x);
        }
        #pragma unroll
        for (int o = 16; o; o >>= 1) {
            dot  += __shfl_xor_sync(0xffffffffu, dot, o);
            asum += __shfl_xor_sync(0xffffffffu, asum, o);
        }
        if (lane == 0) sc[n] = (asum == 0.f) ? NEGV : (dot + pool_b[0]);
    }
    __syncthreads();
    float m = fmaxf(sc[tid], sc[tid + 256]);
    #pragma unroll
    for (int o = 16; o; o >>= 1) m = fmaxf(m, __shfl_xor_sync(0xffffffffu, m, o));
    if (lane == 0) red[warp] = m;
    __syncthreads();
    if (tid == 0) {
        float t = red[0];
        for (int i = 1; i < 8; i++) t = fmaxf(t, red[i]);
        red[0] = t;
    }
    __syncthreads();
    m = red[0];
    float e0 = __expf(sc[tid] - m), e1 = __expf(sc[tid + 256] - m);
    float s = e0 + e1;
    #pragma unroll
    for (int o = 16; o; o >>= 1) s += __shfl_xor_sync(0xffffffffu, s, o);
    if (lane == 0) red2[warp] = s;
    __syncthreads();
    if (tid == 0) {
        float t = 0.f;
        for (int i = 0; i < 8; i++) t += red2[i];
        red2[0] = t;
    }
    __syncthreads();
    float inv = 1.f / red2[0];
    sc[tid] = e0 * inv;
    sc[tid + 256] = e1 * inv;
    __syncthreads();
    float a0 = 0.f, a1 = 0.f, a2 = 0.f;
    #pragma unroll 4
    for (int n = 0; n < SEQ; n++) {
        float p = sc[n];
        const float* vp = v + ((size_t)b * SEQ + n) * HIDDEN;
        a0 += vp[tid] * p;
        a1 += vp[tid + 256] * p;
        a2 += vp[tid + 512] * p;
    }
    g_pooled[b * HIDDEN + tid]       = a0;
    g_pooled[b * HIDDEN + tid + 256] = a1;
    g_pooled[b * HIDDEN + tid + 512] = a2;
}

// ---- routing 2 ----
__global__ __launch_bounds__(384) void route_mlp(const float* __restrict__ w1,
                                                 const float* __restrict__ w2,
                                                 const float* __restrict__ b2) {
    int b = blockIdx.x, tid = threadIdx.x;
    __shared__ float pl[HIDDEN];
    __shared__ float pred[12 * 3];
    for (int d = tid; d < HIDDEN; d += 384) pl[d] = g_pooled[b * HIDDEN + d];
    __syncthreads();
    float acc = 0.f;
    #pragma unroll 16
    for (int k = 0; k < HIDDEN; k++) acc += pl[k] * __ldg(&w1[k * 384 + tid]);
    float hv = fmaxf(acc, 0.f);
    float p0 = hv * w2[tid * 3 + 0];
    float p1 = hv * w2[tid * 3 + 1];
    float p2 = hv * w2[tid * 3 + 2];
    #pragma unroll
    for (int o = 16; o; o >>= 1) {
        p0 += __shfl_xor_sync(0xffffffffu, p0, o);
        p1 += __shfl_xor_sync(0xffffffffu, p1, o);
        p2 += __shfl_xor_sync(0xffffffffu, p2, o);
    }
    int warp = tid >> 5;
    if ((tid & 31) == 0) { pred[warp*3] = p0; pred[warp*3+1] = p1; pred[warp*3+2] = p2; }
    __syncthreads();
    if (tid == 0) {
        float l0 = b2[0], l1 = b2[1], l2 = b2[2];
        for (int w = 0; w < 12; w++) { l0 += pred[w*3]; l1 += pred[w*3+1]; l2 += pred[w*3+2]; }
        float mm = fmaxf(l0, fmaxf(l1, l2));
        float e0 = __expf(l0 - mm), e1 = __expf(l1 - mm), e2 = __expf(l2 - mm);
        float z = e0 + e1 + e2;
        g_alphas[b*3+0] = e0 / z; g_alphas[b*3+1] = e1 / z; g_alphas[b*3+2] = e2 / z;
    }
}

// ---- bf16-split tensor-core GEMM: B via 3-stage cp.async, 2 CTAs/SM ----
// dyn smem: Ah[128x40] @0 (10240B), Al @10240; B stages @20480, each 17408B (Bh 8704 + Bl 8704)
#define GOFF_B 20480
#define GSTG   17408
#define GEMM_SMEM (GOFF_B + 3 * GSTG)

__device__ __forceinline__ void gemm_bf_body(const void* __restrict__ Xv, int xfmt,
                                             const __nv_bfloat16* __restrict__ WH,
                                             const __nv_bfloat16* __restrict__ WL,
                                             const float* __restrict__ bias,
                                             void* __restrict__ outA,
                                             void* __restrict__ outB,
                                             float scale, int omode,
                                             int row0, int col0) {
    extern __shared__ char gsm[];
    __nv_bfloat16* Ah = (__nv_bfloat16*)gsm;                   // [128][40]
    __nv_bfloat16* Al = (__nv_bfloat16*)(gsm + 10240);
    unsigned sb = (unsigned)__cvta_generic_to_shared(gsm);
    int tid = threadIdx.x;
    int wid = tid >> 5, lane = tid & 31;
    int wm = wid & 1, wn = wid >> 1;

    float acc[4][4][4];
    #pragma unroll
    for (int i = 0; i < 4; i++)
        #pragma unroll
        for (int j = 0; j < 4; j++)
            #pragma unroll
            for (int c = 0; c < 4; c++) acc[i][j][c] = 0.f;

    unsigned aaddr_h[4], aaddr_l[4];
    #pragma unroll
    for (int mt = 0; mt < 4; mt++) {
        aaddr_h[mt] = sb + ((wm * 64 + mt * 16 + (lane & 15)) * 40 + ((lane >> 4) << 3)) * 2;
        aaddr_l[mt] = aaddr_h[mt] + 10240;
    }
    unsigned boff[2];
    #pragma unroll
    for (int nb = 0; nb < 2; nb++) {
        int kr = (lane & 7) + (((lane >> 3) & 1) << 3);
        int nc = wn * 32 + nb * 16 + ((lane >> 4) << 3);
        boff[nb] = kr * 272 + nc * 2;
    }

    // B cp.async fill coordinates: per thread 2 chunks per plane
    int br[2], bs[2];
    #pragma unroll
    for (int i = 0; i < 2; i++) {
        int idx = tid + i * 256;
        br[i] = idx >> 4;           // k-row 0..31
        bs[i] = (idx & 15) * 16;    // byte seg in 256B row
    }
    // prologue: stages 0,1
    #pragma unroll
    for (int st = 0; st < 2; st++) {
        unsigned dst = sb + GOFF_B + st * GSTG;
        const __nv_bfloat16* wh = WH + (size_t)(st * 32) * 768 + col0;
        const __nv_bfloat16* wl = WL + (size_t)(st * 32) * 768 + col0;
        #pragma unroll
        for (int i = 0; i < 2; i++) {
            CPA16(dst + br[i] * 272 + bs[i], (const char*)(wh + br[i] * 768) + bs[i]);
            CPA16(dst + 8704 + br[i] * 272 + bs[i], (const char*)(wl + br[i] * 768) + bs[i]);
        }
        CPA_COMMIT();
    }

    for (int it = 0; it < 24; it++) {
        if (it < 23) { CPA_WAIT1(); } else { CPA_WAIT0(); }
        __syncthreads();
        int kt = it * 32;
        // A fill (synchronous; conversion work)
        if (xfmt == 1) {
            const float* Xf = (const float*)Xv;
            #pragma unroll
            for (int i = 0; i < 4; i++) {
                int e = tid + i * 256;
                int r = e >> 3, k0 = (e & 7) * 4;
                float4 x = *(const float4*)&Xf[(size_t)(row0 + r) * 768 + kt + k0];
                unsigned p0 = packbf(x.x), p1 = packbf(x.y);
                unsigned p2 = packbf(x.z), p3 = packbf(x.w);
                *(unsigned*)&Ah[r * 40 + k0]     = __byte_perm(p0, p1, 0x5410);
                *(unsigned*)&Al[r * 40 + k0]     = __byte_perm(p0, p1, 0x7632);
                *(unsigned*)&Ah[r * 40 + k0 + 2] = __byte_perm(p2, p3, 0x5410);
                *(unsigned*)&Al[r * 40 + k0 + 2] = __byte_perm(p2, p3, 0x7632);
            }
        } else {
            const unsigned* Xp = (const unsigned*)Xv;
            #pragma unroll
            for (int i = 0; i < 4; i++) {
                int e = tid + i * 256;
                int r = e >> 3, k0 = (e & 7) * 4;
                uint4 x = *(const uint4*)&Xp[(size_t)(row0 + r) * 768 + kt + k0];
                *(unsigned*)&Ah[r * 40 + k0]     = __byte_perm(x.x, x.y, 0x5410);
                *(unsigned*)&Al[r * 40 + k0]     = __byte_perm(x.x, x.y, 0x7632);
                *(unsigned*)&Ah[r * 40 + k0 + 2] = __byte_perm(x.z, x.w, 0x5410);
                *(unsigned*)&Al[r * 40 + k0 + 2] = __byte_perm(x.z, x.w, 0x7632);
            }
        }
        __syncthreads();
        // issue B prefetch for it+2 into stage (it+2)%3 (safe: not being read)
        if (it < 22) {
            int st = (it + 2) % 3;
            unsigned dst = sb + GOFF_B + st * GSTG;
            const __nv_bfloat16* wh = WH + (size_t)((it + 2) * 32) * 768 + col0;
            const __nv_bfloat16* wl = WL + (size_t)((it + 2) * 32) * 768 + col0;
            #pragma unroll
            for (int i = 0; i < 2; i++) {
                CPA16(dst + br[i] * 272 + bs[i], (const char*)(wh + br[i] * 768) + bs[i]);
                CPA16(dst + 8704 + br[i] * 272 + bs[i], (const char*)(wl + br[i] * 768) + bs[i]);
            }
            CPA_COMMIT();
        }
        // MMA on A smem + B stage it%3
        unsigned bsb = sb + GOFF_B + (it % 3) * GSTG;
        #pragma unroll
        for (int ks = 0; ks < 2; ks++) {
            unsigned koff = ks * 32;
            unsigned ah[4][4], al[4][4], bh[2][4], bl[2][4];
            #pragma unroll
            for (int mt = 0; mt < 4; mt++) {
                LDSM4(ah[mt], aaddr_h[mt] + koff);
                LDSM4(al[mt], aaddr_l[mt] + koff);
            }
            #pragma unroll
            for (int nb = 0; nb < 2; nb++) {
                LDSM4T(bh[nb], bsb + boff[nb] + ks * 16 * 272);
                LDSM4T(bl[nb], bsb + 8704 + boff[nb] + ks * 16 * 272);
            }
            #pragma unroll
            for (int mt = 0; mt < 4; mt++)
                #pragma unroll
                for (int nt = 0; nt < 4; nt++) {
                    unsigned bh0 = bh[nt >> 1][(nt & 1) * 2];
                    unsigned bh1 = bh[nt >> 1][(nt & 1) * 2 + 1];
                    unsigned bl0 = bl[nt >> 1][(nt & 1) * 2];
                    unsigned bl1 = bl[nt >> 1][(nt & 1) * 2 + 1];
                    MMABF(acc[mt][nt], ah[mt], bh0, bh1);
                    MMABF(acc[mt][nt], ah[mt], bl0, bl1);
                    MMABF(acc[mt][nt], al[mt], bh0, bh1);
                }
        }
    }

    int rbase = row0 + wm * 64, cbase = col0 + wn * 32;
    #pragma unroll
    for (int mt = 0; mt < 4; mt++) {
        #pragma unroll
        for (int nt = 0; nt < 4; nt++) {
            int gj = cbase + nt * 8 + (lane & 3) * 2;
            float b0 = __ldg(&bias[gj]), b1 = __ldg(&bias[gj + 1]);
            int r_lo = rbase + mt * 16 + (lane >> 2);
            int r_hi = r_lo + 8;
            float c00 = (acc[mt][nt][0] + b0) * scale;
            float c01 = (acc[mt][nt][1] + b1) * scale;
            float c10 = (acc[mt][nt][2] + b0) * scale;
            float c11 = (acc[mt][nt][3] + b1) * scale;
            if (omode == 1) {
                __nv_bfloat16* ohi = (__nv_bfloat16*)outA;
                __nv_bfloat16* olo = (__nv_bfloat16*)outB;
                unsigned p00 = packbf(c00), p01 = packbf(c01);
                unsigned p10 = packbf(c10), p11 = packbf(c11);
                int bb0 = r_lo >> 9, n0 = r_lo & 511;
                int h = gj >> 6, d = gj & 63;
                size_t o0 = (((size_t)bb0 * HEADS + h) * SEQ + n0) * DK + d;
                *(ushort2*)&ohi[o0] = make_ushort2((unsigned short)p00, (unsigned short)p01);
                *(ushort2*)&olo[o0] = make_ushort2((unsigned short)(p00 >> 16),
                                                   (unsigned short)(p01 >> 16));
                int bb1 = r_hi >> 9, n1 = r_hi & 511;
                size_t o1 = (((size_t)bb1 * HEADS + h) * SEQ + n1) * DK + d;
                *(ushort2*)&ohi[o1] = make_ushort2((unsigned short)p10, (unsigned short)p11);
                *(ushort2*)&olo[o1] = make_ushort2((unsigned short)(p10 >> 16),
                                                   (unsigned short)(p11 >> 16));
            } else {
                float* out = (float*)outA;
                *(float2*)&out[(size_t)r_lo * 768 + gj] = make_float2(c00, c01);
                *(float2*)&out[(size_t)r_hi * 768 + gj] = make_float2(c10, c11);
            }
        }
    }
}

__global__ __launch_bounds__(256, 2) void gemm_qkv_bf(const float* __restrict__ q,
                                                      const float* __restrict__ k,
                                                      const float* __restrict__ v,
                                                      const float* __restrict__ bq,
                                                      const float* __restrict__ bk,
                                                      const float* __restrict__ bv) {
    int z = blockIdx.z;
    const float* X; const float* bias;
    __nv_bfloat16 *oh, *ol; float scale;
    size_t wb = (size_t)z * K2;
    if (z == 0)      { X = q; bias = bq; oh = g_qhH; ol = g_qhL; scale = 0.125f; }
    else if (z == 1) { X = k; bias = bk; oh = g_khH; ol = g_khL; scale = 1.f; }
    else             { X = v; bias = bv; oh = g_vhH; ol = g_vhL; scale = 1.f; }
    gemm_bf_body(X, 1, g_wH + wb, g_wL + wb, bias, oh, ol, scale, 1,
                 blockIdx.y * 128, blockIdx.x * 128);
}

__global__ __launch_bounds__(256, 2) void gemm_out_bf(const float* __restrict__ bias,
                                                      float* __restrict__ out) {
    gemm_bf_body(g_abf, 0, g_wH + (size_t)3 * K2, g_wL + (size_t)3 * K2, bias,
                 out, 0, 1.f, 0, blockIdx.y * 128, blockIdx.x * 128);
}

// ---- fused attention: RT=32, 2 CTAs/SM, cp.async double-buffered fills ----
#define RT 32
#define SPITCH 516
#define OFF_Q  66048
#define OFF_B0 75264
#define OFF_B1 93696
#define ATTN_SMEM 112128
#define PLB 9216

__device__ __forceinline__ void cpa_chunk64(unsigned dst,
                                            const __nv_bfloat16* __restrict__ hi,
                                            const __nv_bfloat16* __restrict__ lo,
                                            int tid) {
    #pragma unroll
    for (int i = 0; i < 2; i++) {
        int idx = tid + i * 256;
        int r = idx >> 3, sg = idx & 7;
        CPA16(dst + r * 144 + sg * 16, hi + r * 64 + sg * 8);
    }
    #pragma unroll
    for (int i = 0; i < 2; i++) {
        int idx = tid + i * 256;
        int r = idx >> 3, sg = idx & 7;
        CPA16(dst + PLB + r * 144 + sg * 16, lo + r * 64 + sg * 8);
    }
}

__global__ __launch_bounds__(256, 2) void attn_kernel() {
    extern __shared__ char smc[];
    float* S = (float*)smc;
    __nv_bfloat16* AhS = (__nv_bfloat16*)(smc + OFF_Q);
    __nv_bfloat16* AlS = (__nv_bfloat16*)(smc + OFF_Q + 4608);
    unsigned sb = (unsigned)__cvta_generic_to_shared(smc);

    int rt = blockIdx.x, h = blockIdx.y, b = blockIdx.z;
    int tid = threadIdx.x;
    int wid = tid >> 5, lane = tid & 31;
    int wm = wid & 1, wn = wid >> 1;

    size_t hoff = ((size_t)(b * HEADS + h)) * SEQ * DK;
    const __nv_bfloat16* QgH = g_qhH + hoff + rt * RT * DK;
    const __nv_bfloat16* QgL = g_qhL + hoff + rt * RT * DK;
    const __nv_bfloat16* KgH = g_khH + hoff;
    const __nv_bfloat16* KgL = g_khL + hoff;
    const __nv_bfloat16* VgH = g_vhH + hoff;
    const __nv_bfloat16* VgL = g_vhL + hoff;

    unsigned bufb0 = sb + OFF_B0, bufb1 = sb + OFF_B1;

    unsigned qrow = (wm * 16 + (lane & 15)) * 144 + ((lane >> 4) << 4);
    unsigned qah = sb + OFF_Q + qrow;
    unsigned qal = qah + 4608;
    unsigned krow = (wn * 16 + (lane & 15)) * 144 + ((lane >> 4) << 4);
    unsigned ka0h = bufb0 + krow, ka0l = ka0h + PLB;
    unsigned ka1h = bufb1 + krow, ka1l = ka1h + PLB;
    int vkr = (lane & 7) + (((lane >> 3) & 1) << 3);
    unsigned vrow = vkr * 144 + wn * 32 + ((lane >> 4) << 4);
    unsigned va0h = bufb0 + vrow, va0l = va0h + PLB;
    unsigned va1h = bufb1 + vrow, va1l = va1h + PLB;

    {
        int r = tid >> 3, sg = tid & 7;
        CPA16(sb + OFF_Q + r * 144 + sg * 16, QgH + r * 64 + sg * 8);
        CPA16(sb + OFF_Q + 4608 + r * 144 + sg * 16, QgL + r * 64 + sg * 8);
    }
    cpa_chunk64(bufb0, KgH, KgL, tid);
    CPA_COMMIT();
    cpa_chunk64(bufb1, KgH + 4096, KgL + 4096, tid);
    CPA_COMMIT();

    // ---- phase 1 ----
    unsigned qfh[4][4], qfl[4][4];
    #pragma unroll
    for (int ch = 0; ch < 8; ch++) {
        if (ch < 7) { CPA_WAIT1(); } else { CPA_WAIT0(); }
        __syncthreads();
        if (ch == 0) {
            #pragma unroll
            for (int kc = 0; kc < 4; kc++) {
                LDSM4(qfh[kc], qah + kc * 32);
                LDSM4(qfl[kc], qal + kc * 32);
            }
        }
        unsigned kh_ = (ch & 1) ? ka1h : ka0h;
        unsigned kl_ = (ch & 1) ? ka1l : ka0l;
        float acc1[2][4];
        #pragma unroll
        for (int j = 0; j < 2; j++)
            #pragma unroll
            for (int c = 0; c < 4; c++) acc1[j][c] = 0.f;
        #pragma unroll
        for (int kc = 0; kc < 4; kc++) {
            unsigned bh[4], bl[4];
            LDSM4(bh, kh_ + kc * 32);
            LDSM4(bl, kl_ + kc * 32);
            #pragma unroll
            for (int nt = 0; nt < 2; nt++) {
                MMABF(acc1[nt], qfh[kc], bh[nt], bh[nt + 2]);
                MMABF(acc1[nt], qfh[kc], bl[nt], bl[nt + 2]);
                MMABF(acc1[nt], qfl[kc], bh[nt], bh[nt + 2]);
            }
        }
        #pragma unroll
        for (int nt = 0; nt < 2; nt++) {
            int r = wm * 16 + (lane >> 2);
            int c = ch * 64 + wn * 16 + nt * 8 + (lane & 3) * 2;
            *(float2*)&S[r * SPITCH + c] = make_float2(acc1[nt][0], acc1[nt][1]);
            *(float2*)&S[(r + 8) * SPITCH + c] = make_float2(acc1[nt][2], acc1[nt][3]);
        }
        __syncthreads();
        if (ch < 6) {
            cpa_chunk64((ch & 1) ? bufb1 : bufb0,
                        KgH + (ch + 2) * 4096, KgL + (ch + 2) * 4096, tid);
            CPA_COMMIT();
        }
    }

    cpa_chunk64(bufb0, VgH, VgL, tid);
    CPA_COMMIT();
    cpa_chunk64(bufb1, VgH + 4096, VgL + 4096, tid);
    CPA_COMMIT();

    // ---- phase 2 ----
    float wa0g = __ldg(&g_alphas[b*3+0]);
    float wa1g = __ldg(&g_alphas[b*3+1]);
    float wa2g = __ldg(&g_alphas[b*3+2]);
    for (int r = wid; r < RT; r += 8) {
        float* Sr = S + r * SPITCH;
        int n = rt * RT + r;
        const unsigned* p0 = g_packed + ((size_t)(0*BATCH + b) * SEQ + n) * 16;
        const unsigned* p1 = g_packed + ((size_t)(1*BATCH + b) * SEQ + n) * 16;
        const unsigned* p2 = g_packed + ((size_t)(2*BATCH + b) * SEQ + n) * 16;

        float mx = -1e30f;
        #pragma unroll
        for (int it = 0; it < 16; it++) mx = fmaxf(mx, Sr[it * 32 + lane]);
        #pragma unroll
        for (int o = 16; o; o >>= 1) mx = fmaxf(mx, __shfl_xor_sync(0xffffffffu, mx, o));

        float z0 = 0.f, z1 = 0.f, z2 = 0.f;
        #pragma unroll
        for (int it = 0; it < 16; it++) {
            int c = it * 32 + lane;
            float e = __expf(Sr[c] - mx);
            Sr[c] = e;
            unsigned w0 = __ldg(p0 + it), w1 = __ldg(p1 + it), w2 = __ldg(p2 + it);
            if (!((w0 >> lane) & 1)) z0 += e;
            if (!((w1 >> lane) & 1)) z1 += e;
            if (!((w2 >> lane) & 1)) z2 += e;
        }
        #pragma unroll
        for (int o = 16; o; o >>= 1) {
            z0 += __shfl_xor_sync(0xffffffffu, z0, o);
            z1 += __shfl_xor_sync(0xffffffffu, z1, o);
            z2 += __shfl_xor_sync(0xffffffffu, z2, o);
        }
        float wa0 = wa0g / z0, wa1 = wa1g / z1, wa2 = wa2g / z2;
        #pragma unroll
        for (int it = 0; it < 16; it++) {
            int c = it * 32 + lane;
            unsigned w0 = __ldg(p0 + it), w1 = __ldg(p1 + it), w2 = __ldg(p2 + it);
            float coef = (((w0 >> lane) & 1) ? 0.f : wa0)
                       + (((w1 >> lane) & 1) ? 0.f : wa1)
                       + (((w2 >> lane) & 1) ? 0.f : wa2);
            Sr[c] *= coef;
        }
    }

    // ---- phase 3 ----
    float acc3[2][4];
    #pragma unroll
    for (int j = 0; j < 2; j++)
        #pragma unroll
        for (int c = 0; c < 4; c++) acc3[j][c] = 0.f;

    #pragma unroll
    for (int ch = 0; ch < 8; ch++) {
        if (ch < 7) { CPA_WAIT1(); } else { CPA_WAIT0(); }
        __syncthreads();
        #pragma unroll
        for (int i = 0; i < 4; i++) {
            int idx = tid + i * 256;
            int r = idx >> 5, c2 = (idx & 31) * 2;
            float2 v2 = *(const float2*)&S[r * SPITCH + ch * 64 + c2];
            unsigned pa = packbf(v2.x), pb = packbf(v2.y);
            *(unsigned*)&AhS[r * 72 + c2] = __byte_perm(pa, pb, 0x5410);
            *(unsigned*)&AlS[r * 72 + c2] = __byte_perm(pa, pb, 0x7632);
        }
        __syncthreads();
        unsigned vh_ = (ch & 1) ? va1h : va0h;
        unsigned vl_ = (ch & 1) ? va1l : va0l;
        #pragma unroll
        for (int kc = 0; kc < 4; kc++) {
            unsigned koff = kc * 32, voff = kc * 2304;
            unsigned ah[4], al[4], bh[4], bl[4];
            LDSM4(ah, qah + koff);
            LDSM4(al, qal + koff);
            LDSM4T(bh, vh_ + voff);
            LDSM4T(bl, vl_ + voff);
            #pragma unroll
            for (int nt = 0; nt < 2; nt++) {
                MMABF(acc3[nt], ah, bh[nt * 2], bh[nt * 2 + 1]);
                MMABF(acc3[nt], ah, bl[nt * 2], bl[nt * 2 + 1]);
                MMABF(acc3[nt], al, bh[nt * 2], bh[nt * 2 + 1]);
            }
        }
        __syncthreads();
        if (ch < 6) {
            cpa_chunk64((ch & 1) ? bufb1 : bufb0,
                        VgH + (ch + 2) * 4096, VgL + (ch + 2) * 4096, tid);
            CPA_COMMIT();
        }
    }

    #pragma unroll
    for (int nt = 0; nt < 2; nt++) {
        int r = wm * 16 + (lane >> 2);
        int c = wn * 16 + nt * 8 + (lane & 3) * 2;
        size_t off0 = (size_t)(b * SEQ + rt * RT + r) * HIDDEN + h * 64 + c;
        size_t off1 = (size_t)(b * SEQ + rt * RT + r + 8) * HIDDEN + h * 64 + c;
        *(uint2*)&g_abf[off0] = make_uint2(packbf(acc3[nt][0]), packbf(acc3[nt][1]));
        *(uint2*)&g_abf[off1] = make_uint2(packbf(acc3[nt][2]), packbf(acc3[nt][3]));
    }
}

// ---- launch ----
extern "C" void kernel_launch(void* const* d_in, const int* in_sizes, int n_in,
                              void* d_out, int out_size) {
    const float* v = (const float*)d_in[0];
    const float* k = (const float*)d_in[1];
    const float* q = (const float*)d_in[2];
    const void*  masks = d_in[3];
    const float* Wv = (const float*)d_in[6];
    const float* bv = (const float*)d_in[7];
    const float* Wk = (const float*)d_in[8];
    const float* bk = (const float*)d_in[9];
    const float* Wq = (const float*)d_in[10];
    const float* bq = (const float*)d_in[11];
    const float* Wm = (const float*)d_in[12];
    const float* bm = (const float*)d_in[13];
    const float* pool_w = (const float*)d_in[14];
    const float* pool_b = (const float*)d_in[15];
    const float* w1 = (const float*)d_in[16];
    const float* w2 = (const float*)d_in[17];
    const float* b2 = (const float*)d_in[18];
    float* out = (float*)d_out;

    static cudaStream_t s1 = 0, s2 = 0;
    static cudaEvent_t evR = 0, ev1 = 0, ev2 = 0, ev3 = 0;
    if (!s1) {
        cudaStreamCreateWithFlags(&s1, cudaStreamNonBlocking);
        cudaStreamCreateWithFlags(&s2, cudaStreamNonBlocking);
        cudaEventCreateWithFlags(&evR, cudaEventDisableTiming);
        cudaEventCreateWithFlags(&ev1, cudaEventDisableTiming);
        cudaEventCreateWithFlags(&ev2, cudaEventDisableTiming);
        cudaEventCreateWithFlags(&ev3, cudaEventDisableTiming);
        cudaFuncSetAttribute(attn_kernel, cudaFuncAttributeMaxDynamicSharedMemorySize, ATTN_SMEM);
        cudaFuncSetAttribute(gemm_qkv_bf, cudaFuncAttributeMaxDynamicSharedMemorySize, GEMM_SMEM);
        cudaFuncSetAttribute(gemm_out_bf, cudaFuncAttributeMaxDynamicSharedMemorySize, GEMM_SMEM);
    }

    cudaEventRecord(evR, 0);
    cudaStreamWaitEvent(s1, evR, 0);
    cudaStreamWaitEvent(s2, evR, 0);

    // s1: routing branch
    route_pool<<<BATCH, 256, 0, s1>>>(v, pool_w, pool_b);
    route_mlp<<<BATCH, 384, 0, s1>>>(w1, w2, b2);
    cudaEventRecord(ev1, s1);

    // s2: weight conversion FIRST (gates QKV), then mask branch
    conv_w<<<dim3(K2 / 1024, 4), 256, 0, s2>>>(Wq, Wk, Wv, Wm);
    cudaEventRecord(ev2, s2);
    zero_flags<<<1, 1, 0, s2>>>();
    detect_mask_mode<<<16, 256, 0, s2>>>((const unsigned*)masks);
    pack_masks<<<ORDERS * BATCH * SEQ / 8, 256, 0, s2>>>(masks);
    cudaEventRecord(ev3, s2);

    // main: QKV projections after weights ready
    cudaStreamWaitEvent(0, ev2, 0);
    dim3 gq(HIDDEN / 128, (BATCH * SEQ) / 128, 3);
    gemm_qkv_bf<<<gq, 256, GEMM_SMEM>>>(q, k, v, bq, bk, bv);

    cudaStreamWaitEvent(0, ev1, 0);
    cudaStreamWaitEvent(0, ev3, 0);

    attn_kernel<<<dim3(SEQ / RT, HEADS, BATCH), 256, ATTN_SMEM>>>();

    dim3 gg(HIDDEN / 128, (BATCH * SEQ) / 128);
    gemm_out_bf<<<gg, 256, GEMM_SMEM>>>(bm, out);
}